// round 8
// baseline (speedup 1.0000x reference)
#include <cuda_runtime.h>
#include <cstdint>

#define N_SRC   100000
#define N_TGT   50000
#define N_EDGES 600000
#define CH      128
#define NREL    7
#define NTYP    4
#define NSEG    11
#define NCHUNK  44          // NSEG * (128/32)

// GEMM tiling: CTA 128x128, 8 warps in 2x4 grid, warp tile 64x32
#define TILE_M  128
#define SSTR    36                      // padded row stride (words)
#define A_WORDS (TILE_M * SSTR)         // 4608
#define B_WORDS (128 * SSTR)            // 4608
#define STAGE_WORDS (A_WORDS + B_WORDS) // 9216
#define STAGE_BYTES (STAGE_WORDS * 4)   // 36864
#define NSTAGE  3
#define GSMEM_BYTES (NSTAGE * STAGE_BYTES)   // 110592

// Scratch (allocation-free rule: __device__ globals)
__device__ float    g_agg[(size_t)N_TGT * NREL * CH];   // pre-normalized sums
__device__ float    g_cnt[N_TGT * NREL];
__device__ uint32_t g_wtf32[NSEG * CH * CH];            // tf32 weights, seg-major

__device__ __forceinline__ uint32_t to_tf32(float x) {
    uint32_t r;
    asm("cvt.rna.tf32.f32 %0, %1;" : "=r"(r) : "f"(x));
    return r;
}
__device__ __forceinline__ uint32_t smem_u32(const void* p) {
    uint32_t a;
    asm("{ .reg .u64 t; cvta.to.shared.u64 t, %1; cvt.u32.u64 %0, t; }" : "=r"(a) : "l"(p));
    return a;
}
__device__ __forceinline__ void cp16(uint32_t dst, const void* src, bool pred) {
    asm volatile("cp.async.ca.shared.global [%0], [%1], 16, %2;"
                 :: "r"(dst), "l"(src), "r"(pred ? 16 : 0) : "memory");
}
#define CP_COMMIT() asm volatile("cp.async.commit_group;" ::: "memory")
#define CP_WAIT(n)  asm volatile("cp.async.wait_group %0;" :: "n"(n) : "memory")

#define LDSM_X4(r0, r1, r2, r3, addr) \
    asm volatile("ldmatrix.sync.aligned.m8n8.x4.shared.b16 {%0,%1,%2,%3}, [%4];" \
        : "=r"(r0), "=r"(r1), "=r"(r2), "=r"(r3) : "r"(addr))

__device__ __forceinline__ void mma_tf32(float* c,
    uint32_t a0, uint32_t a1, uint32_t a2, uint32_t a3,
    uint32_t b0, uint32_t b1)
{
    asm volatile(
        "mma.sync.aligned.m16n8k8.row.col.f32.tf32.tf32.f32 "
        "{%0,%1,%2,%3}, {%4,%5,%6,%7}, {%8,%9}, {%0,%1,%2,%3};"
        : "+f"(c[0]), "+f"(c[1]), "+f"(c[2]), "+f"(c[3])
        : "r"(a0), "r"(a1), "r"(a2), "r"(a3), "r"(b0), "r"(b1));
}

// ---------------- kernel 0: weight pre-convert ----------------
__global__ __launch_bounds__(256) void prep_weights(
    const float* __restrict__ relw, const float* __restrict__ rootw,
    uint32_t* __restrict__ wt)
{
    int i = blockIdx.x * 256 + threadIdx.x;
    const int NREL4 = NREL * CH * CH / 4;
    const int TOT4  = NSEG * CH * CH / 4;
    if (i >= TOT4) return;
    float4 v = (i < NREL4) ? ((const float4*)relw)[i]
                           : ((const float4*)rootw)[i - NREL4];
    uint4 w;
    w.x = to_tf32(v.x); w.y = to_tf32(v.y);
    w.z = to_tf32(v.z); w.w = to_tf32(v.w);
    ((uint4*)wt)[i] = w;
}

// ---------------- kernel 1: edge degree count ----------------
__global__ __launch_bounds__(256) void count_kernel(
    const int* __restrict__ edst, const int* __restrict__ etyp,
    float* __restrict__ cnt)
{
    int e = blockIdx.x * 256 + threadIdx.x;
    if (e >= N_EDGES) return;
    int d = __ldg(edst + e);
    int t = __ldg(etyp + e);
    asm volatile("red.global.add.f32 [%0], %1;"
                 :: "l"(cnt + d * NREL + t), "f"(1.0f) : "memory");
}

// ---------------- kernel 2: normalized edge scatter ----------------
__global__ __launch_bounds__(256) void scatter_kernel(
    const float* __restrict__ xs,
    const int* __restrict__ esrc, const int* __restrict__ edst,
    const int* __restrict__ etyp, const float* __restrict__ cnt,
    float* __restrict__ agg)
{
    int w = (blockIdx.x * 256 + threadIdx.x) >> 5;
    int lane = threadIdx.x & 31;
    if (w >= N_EDGES) return;
    int s = __ldg(esrc + w);
    int d = __ldg(edst + w);
    int t = __ldg(etyp + w);
    float inv = 1.0f / fmaxf(__ldg(cnt + d * NREL + t), 1.0f);
    float4 v = ((const float4*)(xs + ((size_t)s << 7)))[lane];
    v.x *= inv; v.y *= inv; v.z *= inv; v.w *= inv;
    float* base = agg + (((size_t)d * NREL + t) << 7) + (lane << 2);
    asm volatile("red.global.add.v4.f32 [%0], {%1,%2,%3,%4};"
                 :: "l"(base), "f"(v.x), "f"(v.y), "f"(v.z), "f"(v.w) : "memory");
}

// ---------------- kernel 3: pipelined tf32 GEMM, 128x128 CTA tile ---------
__global__ __launch_bounds__(256, 2) void gemm_mma_kernel(
    const float* __restrict__ agg, const uint32_t* __restrict__ wt,
    const float* __restrict__ xt, const float* __restrict__ rootb,
    const int* __restrict__ ttype, float* __restrict__ out)
{
    extern __shared__ uint32_t smw[];
    __shared__ int sTyp[TILE_M];

    const int tid = threadIdx.x;
    const int wid = tid >> 5;
    const int lid = tid & 31;
    const int wm = wid & 1;        // 64-row half
    const int wn = wid >> 1;       // 32-col quarter
    const int row0 = blockIdx.x * TILE_M;
    const uint32_t sb = smem_u32(smw);

    if (tid < TILE_M) {
        int g = row0 + tid;
        sTyp[tid] = (g < N_TGT) ? ttype[g] : -1;
    }
    __syncthreads();

    auto issue_chunk = [&](int ci, int stage) {
        int seg = ci >> 2;
        int k0  = (ci & 3) << 5;
        uint32_t aB = sb + stage * STAGE_BYTES;
        uint32_t bB = aB + A_WORDS * 4;
#pragma unroll
        for (int j = 0; j < 4; ++j) {
            int i = tid + (j << 8);            // 0..1023
            int row = i >> 3, kv = i & 7;
            int g = row0 + row;
            bool ok = (g < N_TGT);
            int gc = ok ? g : 0;
            const float* src;
            if (seg < NREL) {
                src = agg + (((size_t)gc * NREL + seg) << 7) + k0 + (kv << 2);
            } else {
                ok = ok && (sTyp[row] == seg - NREL);
                src = xt + ((size_t)gc << 7) + k0 + (kv << 2);
            }
            cp16(aB + row * (SSTR * 4) + (kv << 4), src, ok);
        }
        const uint32_t* wsrc = wt + ((size_t)seg << 14) + k0;
#pragma unroll
        for (int j = 0; j < 4; ++j) {
            int i = tid + (j << 8);            // 0..1023
            int c = i >> 3, kv = i & 7;
            cp16(bB + c * (SSTR * 4) + (kv << 4), wsrc + (c << 7) + (kv << 2), true);
        }
    };

    float acc[4][4][4];
#pragma unroll
    for (int mi = 0; mi < 4; ++mi)
#pragma unroll
        for (int ni = 0; ni < 4; ++ni)
#pragma unroll
            for (int q = 0; q < 4; ++q) acc[mi][ni][q] = 0.0f;

    // prologue: fill all 3 stages
#pragma unroll
    for (int p = 0; p < NSTAGE; ++p) { issue_chunk(p, p); CP_COMMIT(); }

    // ldmatrix lane addressing (proven in R7):
    // A x4: lanes {0-7: r0-7 k0-3, 8-15: r8-15 k0-3, 16-23: r0-7 k4-7, 24-31: r8-15 k4-7}
    const uint32_t laneA = (uint32_t)(((wm << 6) + (lid & 15)) * (SSTR * 4)
                                      + ((lid >> 4) << 4));
    // B x4: lanes {0-7: n0-7 k0-3, 8-15: n0-7 k4-7, 16-23: n8-15 k0-3, 24-31: n8-15 k4-7}
    const uint32_t laneB = (uint32_t)((((wn << 5) + ((lid >> 4) << 3) + (lid & 7)) * (SSTR * 4))
                                      + (((lid >> 3) & 1) << 4));
    const uint32_t MI_OFF = 16u * SSTR * 4;   // 16 rows
    const uint32_t NI_OFF = 16u * SSTR * 4;   // 16 cols

    for (int ci = 0; ci < NCHUNK; ++ci) {
        int stage = ci % NSTAGE;
        CP_WAIT(NSTAGE - 1);           // chunk ci arrived (this thread)
        __syncthreads();               // ...and for all threads
        const uint32_t aA = sb + stage * STAGE_BYTES + laneA;
        const uint32_t bA = sb + stage * STAGE_BYTES + A_WORDS * 4 + laneB;
#pragma unroll
        for (int ks = 0; ks < 4; ++ks) {
            const uint32_t ko = (uint32_t)(ks << 5);   // 8 k-words = 32 bytes
            uint32_t b01[4], b23[4];
            LDSM_X4(b01[0], b01[1], b01[2], b01[3], bA + ko);
            LDSM_X4(b23[0], b23[1], b23[2], b23[3], bA + NI_OFF + ko);
#pragma unroll
            for (int mi = 0; mi < 4; ++mi) {
                uint32_t a[4];
                LDSM_X4(a[0], a[1], a[2], a[3], aA + mi * MI_OFF + ko);
                mma_tf32(acc[mi][0], a[0], a[1], a[2], a[3], b01[0], b01[1]);
                mma_tf32(acc[mi][1], a[0], a[1], a[2], a[3], b01[2], b01[3]);
                mma_tf32(acc[mi][2], a[0], a[1], a[2], a[3], b23[0], b23[1]);
                mma_tf32(acc[mi][3], a[0], a[1], a[2], a[3], b23[2], b23[3]);
            }
        }
        __syncthreads();               // all warps done with this stage
        if (ci + NSTAGE < NCHUNK) issue_chunk(ci + NSTAGE, stage);
        CP_COMMIT();                   // keep group accounting uniform
    }

    // ---- epilogue: bias + store ----
#pragma unroll
    for (int mi = 0; mi < 4; ++mi) {
#pragma unroll
        for (int half = 0; half < 2; ++half) {
            int row = (wm << 6) + (mi << 4) + (half << 3) + (lid >> 2);
            int g = row0 + row;
            if (g >= N_TGT) continue;
            int t = sTyp[row];
#pragma unroll
            for (int ni = 0; ni < 4; ++ni) {
                int col = (wn << 5) + (ni << 3) + ((lid & 3) << 1);
                float2 o;
                o.x = acc[mi][ni][half * 2 + 0] + rootb[(t << 7) + col];
                o.y = acc[mi][ni][half * 2 + 1] + rootb[(t << 7) + col + 1];
                *(float2*)(out + ((size_t)g << 7) + col) = o;
            }
        }
    }
}

extern "C" void kernel_launch(void* const* d_in, const int* in_sizes, int n_in,
                              void* d_out, int out_size)
{
    const float* x_src  = (const float*)d_in[0];
    const float* x_tgt  = (const float*)d_in[1];
    const float* rel_w  = (const float*)d_in[2];
    const float* root_w = (const float*)d_in[3];
    const float* root_b = (const float*)d_in[4];
    const int*   e_src  = (const int*)d_in[5];
    const int*   e_dst  = (const int*)d_in[6];
    const int*   e_typ  = (const int*)d_in[7];
    const int*   n_typ  = (const int*)d_in[8];
    float* out = (float*)d_out;

    void *aggp = nullptr, *cntp = nullptr, *wtp = nullptr;
    cudaGetSymbolAddress(&aggp, g_agg);
    cudaGetSymbolAddress(&cntp, g_cnt);
    cudaGetSymbolAddress(&wtp,  g_wtf32);
    cudaMemsetAsync(aggp, 0, (size_t)N_TGT * NREL * CH * sizeof(float));
    cudaMemsetAsync(cntp, 0, (size_t)N_TGT * NREL * sizeof(float));

    prep_weights<<<(NSEG * CH * CH / 4 + 255) / 256, 256>>>(rel_w, root_w, (uint32_t*)wtp);
    count_kernel<<<(N_EDGES + 255) / 256, 256>>>(e_dst, e_typ, (float*)cntp);
    scatter_kernel<<<N_EDGES / 8, 256>>>(x_src, e_src, e_dst, e_typ,
                                         (const float*)cntp, (float*)aggp);

    cudaFuncSetAttribute(gemm_mma_kernel,
                         cudaFuncAttributeMaxDynamicSharedMemorySize, GSMEM_BYTES);
    gemm_mma_kernel<<<(N_TGT + TILE_M - 1) / TILE_M, 256, GSMEM_BYTES>>>(
        (const float*)aggp, (const uint32_t*)wtp, x_tgt, root_b, n_typ, out);
}

// round 10
// speedup vs baseline: 1.0893x; 1.0893x over previous
#include <cuda_runtime.h>
#include <cstdint>

#define N_SRC   100000
#define N_TGT   50000
#define N_EDGES 600000
#define CH      128
#define NREL    7
#define NTYP    4
#define NSEG    11
#define NBINS   (N_TGT * NREL)          // 350000
#define NPART   342                     // ceil(NBINS/1024)

// Fused kernel tiling
#define TILE_M  64
#define ASTR    132                     // A row stride (words): 128 + 4 pad
#define A_BYTES (TILE_M * ASTR * 4)     // 33792 per buffer
#define BSTR    36                      // B row stride (words)
#define B_BYTES (128 * BSTR * 4)        // 18432 per stage
#define ELIST_CAP 1536

#define OFF_A0  0
#define OFF_A1  A_BYTES
#define OFF_B0  (2 * A_BYTES)
#define OFF_B1  (2 * A_BYTES + B_BYTES)
#define OFF_OFS (2 * A_BYTES + 2 * B_BYTES)
#define OFF_TYP (OFF_OFS + 452 * 4)
#define OFF_EL  (OFF_TYP + 64 * 4)
#define SMEM_TOTAL (OFF_EL + ELIST_CAP * 4)   // 112656 bytes -> 2 CTAs/SM

// Scratch (allocation-free rule: __device__ globals)
__device__ uint32_t g_bincnt[NBINS];
__device__ uint32_t g_cursor[NBINS];
__device__ uint32_t g_binofs[NBINS + 1];
__device__ uint32_t g_part[NPART];
__device__ uint32_t g_elist[N_EDGES];
__device__ uint32_t g_wtf32[NSEG * CH * CH];

// ---------------- helpers ----------------
__device__ __forceinline__ uint32_t to_tf32(float x) {
    uint32_t r;
    asm("cvt.rna.tf32.f32 %0, %1;" : "=r"(r) : "f"(x));
    return r;
}
__device__ __forceinline__ uint32_t smem_u32(const void* p) {
    uint32_t a;
    asm("{ .reg .u64 t; cvta.to.shared.u64 t, %1; cvt.u32.u64 %0, t; }" : "=r"(a) : "l"(p));
    return a;
}
__device__ __forceinline__ void cp16(uint32_t dst, const void* src, bool pred) {
    asm volatile("cp.async.ca.shared.global [%0], [%1], 16, %2;"
                 :: "r"(dst), "l"(src), "r"(pred ? 16 : 0) : "memory");
}
#define CP_COMMIT() asm volatile("cp.async.commit_group;" ::: "memory")
#define CP_WAIT(n)  asm volatile("cp.async.wait_group %0;" :: "n"(n) : "memory")
#define BAR_SYNC(id, cnt)   asm volatile("bar.sync %0, %1;"   :: "r"(id), "r"(cnt) : "memory")
#define BAR_ARRIVE(id, cnt) asm volatile("bar.arrive %0, %1;" :: "r"(id), "r"(cnt) : "memory")
#define LDSM_X4(r0, r1, r2, r3, addr) \
    asm volatile("ldmatrix.sync.aligned.m8n8.x4.shared.b16 {%0,%1,%2,%3}, [%4];" \
        : "=r"(r0), "=r"(r1), "=r"(r2), "=r"(r3) : "r"(addr))

__device__ __forceinline__ void mma_tf32(float* c,
    uint32_t a0, uint32_t a1, uint32_t a2, uint32_t a3,
    uint32_t b0, uint32_t b1)
{
    asm volatile(
        "mma.sync.aligned.m16n8k8.row.col.f32.tf32.tf32.f32 "
        "{%0,%1,%2,%3}, {%4,%5,%6,%7}, {%8,%9}, {%0,%1,%2,%3};"
        : "+f"(c[0]), "+f"(c[1]), "+f"(c[2]), "+f"(c[3])
        : "r"(a0), "r"(a1), "r"(a2), "r"(a3), "r"(b0), "r"(b1));
}

// ---------------- CSR build ----------------
__global__ __launch_bounds__(256) void hist_kernel(
    const int* __restrict__ edst, const int* __restrict__ etyp,
    uint32_t* __restrict__ cnt)
{
    int e = blockIdx.x * 256 + threadIdx.x;
    if (e >= N_EDGES) return;
    atomicAdd(&cnt[__ldg(edst + e) * NREL + __ldg(etyp + e)], 1u);
}

__global__ __launch_bounds__(1024) void scanA_kernel(
    const uint32_t* __restrict__ cnt, uint32_t* __restrict__ part)
{
    __shared__ uint32_t s[1024];
    int t = threadIdx.x;
    int i = blockIdx.x * 1024 + t;
    s[t] = (i < NBINS) ? cnt[i] : 0u;
    __syncthreads();
    for (int off = 512; off; off >>= 1) {
        if (t < off) s[t] += s[t + off];
        __syncthreads();
    }
    if (t == 0) part[blockIdx.x] = s[0];
}

__global__ __launch_bounds__(512) void scanB_kernel(uint32_t* __restrict__ part)
{
    __shared__ uint32_t s[512];
    int t = threadIdx.x;
    uint32_t v = (t < NPART) ? part[t] : 0u;
    s[t] = v;
    __syncthreads();
    for (int off = 1; off < 512; off <<= 1) {
        uint32_t x = (t >= off) ? s[t - off] : 0u;
        __syncthreads();
        s[t] += x;
        __syncthreads();
    }
    if (t < NPART) part[t] = s[t] - v;     // exclusive
}

__global__ __launch_bounds__(1024) void scanC_kernel(
    const uint32_t* __restrict__ cnt, const uint32_t* __restrict__ part,
    uint32_t* __restrict__ ofs)
{
    __shared__ uint32_t s[1024];
    int t = threadIdx.x;
    int i = blockIdx.x * 1024 + t;
    uint32_t v = (i < NBINS) ? cnt[i] : 0u;
    s[t] = v;
    __syncthreads();
    for (int off = 1; off < 1024; off <<= 1) {
        uint32_t x = (t >= off) ? s[t - off] : 0u;
        __syncthreads();
        s[t] += x;
        __syncthreads();
    }
    if (i < NBINS) ofs[i] = s[t] - v + part[blockIdx.x];
    if (blockIdx.x == 0 && t == 0) ofs[NBINS] = N_EDGES;
}

__global__ __launch_bounds__(256) void fill_kernel(
    const int* __restrict__ esrc, const int* __restrict__ edst,
    const int* __restrict__ etyp,
    const uint32_t* __restrict__ ofs, uint32_t* __restrict__ cursor,
    uint32_t* __restrict__ elist)
{
    int e = blockIdx.x * 256 + threadIdx.x;
    if (e >= N_EDGES) return;
    int bin = __ldg(edst + e) * NREL + __ldg(etyp + e);
    uint32_t pos = ofs[bin] + atomicAdd(&cursor[bin], 1u);
    elist[pos] = (uint32_t)__ldg(esrc + e);
}

// ---------------- weight pre-convert ----------------
__global__ __launch_bounds__(256) void prep_weights(
    const float* __restrict__ relw, const float* __restrict__ rootw,
    uint32_t* __restrict__ wt)
{
    int i = blockIdx.x * 256 + threadIdx.x;
    const int NREL4 = NREL * CH * CH / 4;
    const int TOT4  = NSEG * CH * CH / 4;
    if (i >= TOT4) return;
    float4 v = (i < NREL4) ? ((const float4*)relw)[i]
                           : ((const float4*)rootw)[i - NREL4];
    uint4 w;
    w.x = to_tf32(v.x); w.y = to_tf32(v.y);
    w.z = to_tf32(v.z); w.w = to_tf32(v.w);
    ((uint4*)wt)[i] = w;
}

// ---------------- fused warp-specialized aggregate+GEMM ----------------
// Warps 0-3: consumers (MMA, 64x32 warp tile each).  Warps 4-7: producers
// (gather-aggregate relation A tiles; masked-copy root A tiles).
// Named barriers: 1/4 = A buf even/odd ready; 3/5 = A buf even/odd free;
// 2 = consumer-local B staging.
__global__ __launch_bounds__(256, 2) void fused_kernel(
    const float* __restrict__ xs, const float* __restrict__ xt,
    const uint32_t* __restrict__ wt, const float* __restrict__ rootb,
    const int* __restrict__ ttype,
    const uint32_t* __restrict__ binofs, const uint32_t* __restrict__ elist,
    float* __restrict__ out)
{
    extern __shared__ char smc[];
    const uint32_t sb = smem_u32(smc);
    uint32_t* sOfs = (uint32_t*)(smc + OFF_OFS);
    int*      sTyp = (int*)(smc + OFF_TYP);
    uint32_t* sEl  = (uint32_t*)(smc + OFF_EL);

    const int tid = threadIdx.x;
    const int wid = tid >> 5;
    const int lid = tid & 31;
    const int row0 = blockIdx.x * TILE_M;

    // preload CSR offsets (449 used) + node types
    for (int i = tid; i < 449; i += 256) {
        int idx = row0 * NREL + i;
        if (idx > NBINS) idx = NBINS;
        sOfs[i] = binofs[idx];
    }
    if (tid < TILE_M) {
        int g = row0 + tid;
        sTyp[tid] = (g < N_TGT) ? ttype[g] : -1;
    }
    __syncthreads();
    const uint32_t e0 = sOfs[0];
    const int nEdge = (int)(sOfs[448] - e0);
    const bool useS = (nEdge <= ELIST_CAP);
    if (useS)
        for (int i = tid; i < nEdge; i += 256) sEl[i] = elist[e0 + i];
    __syncthreads();

    if (wid < 4) {
        // ================= consumer =================
        const int wn = wid;
        float acc[4][4][4];
#pragma unroll
        for (int mi = 0; mi < 4; ++mi)
#pragma unroll
            for (int ni = 0; ni < 4; ++ni)
#pragma unroll
                for (int q = 0; q < 4; ++q) acc[mi][ni][q] = 0.0f;

        auto issueB = [&](int ci, int stage) {
            int seg = ci >> 2, k0 = (ci & 3) << 5;
            const uint32_t* wsrc = wt + ((size_t)seg << 14) + k0;
            uint32_t bB = sb + (stage ? OFF_B1 : OFF_B0);
#pragma unroll
            for (int j = 0; j < 8; ++j) {
                int i = tid + (j << 7);        // 0..1023
                int c = i >> 3, kv = i & 7;
                cp16(bB + c * (BSTR * 4) + (kv << 4), wsrc + (c << 7) + (kv << 2), true);
            }
        };
        issueB(0, 0); CP_COMMIT();
        issueB(1, 1); CP_COMMIT();

        // ldmatrix lane addressing (R7-proven pattern)
        const uint32_t laneA = (uint32_t)((lid & 15) * (ASTR * 4) + ((lid >> 4) << 4));
        const uint32_t laneB = (uint32_t)(((wn << 5) + ((lid >> 4) << 3) + (lid & 7)) * (BSTR * 4)
                                          + (((lid >> 3) & 1) << 4));

        for (int ci = 0; ci < 44; ++ci) {
            int seg = ci >> 2, stage = ci & 1, buf = seg & 1;
            if ((ci & 3) == 0) BAR_SYNC(buf ? 4 : 1, 256);   // A[seg] ready
            CP_WAIT(1);                                      // B chunk ci landed (this thread)
            BAR_SYNC(2, 128);                                // ...and for all consumers
            const uint32_t aA = sb + (buf ? OFF_A1 : OFF_A0) + laneA + ((uint32_t)(ci & 3) << 7);
            const uint32_t bA = sb + (stage ? OFF_B1 : OFF_B0) + laneB;
#pragma unroll
            for (int ks = 0; ks < 4; ++ks) {
                const uint32_t ko = (uint32_t)(ks << 5);
                uint32_t b01[4], b23[4];
                LDSM_X4(b01[0], b01[1], b01[2], b01[3], bA + ko);
                LDSM_X4(b23[0], b23[1], b23[2], b23[3], bA + 16u * BSTR * 4 + ko);
#pragma unroll
                for (int mi = 0; mi < 4; ++mi) {
                    uint32_t a[4];
                    LDSM_X4(a[0], a[1], a[2], a[3], aA + (uint32_t)mi * (16 * ASTR * 4) + ko);
                    mma_tf32(acc[mi][0], a[0], a[1], a[2], a[3], b01[0], b01[1]);
                    mma_tf32(acc[mi][1], a[0], a[1], a[2], a[3], b01[2], b01[3]);
                    mma_tf32(acc[mi][2], a[0], a[1], a[2], a[3], b23[0], b23[1]);
                    mma_tf32(acc[mi][3], a[0], a[1], a[2], a[3], b23[2], b23[3]);
                }
            }
            BAR_SYNC(2, 128);                 // all consumers done with B stage
            if (ci + 2 < 44) issueB(ci + 2, stage);
            CP_COMMIT();                      // uniform group accounting
            if ((ci & 3) == 3) BAR_ARRIVE(buf ? 5 : 3, 256);  // A[seg] free
        }

        // epilogue: bias + store
#pragma unroll
        for (int mi = 0; mi < 4; ++mi) {
#pragma unroll
            for (int half = 0; half < 2; ++half) {
                int row = (mi << 4) + (half << 3) + (lid >> 2);
                int g = row0 + row;
                if (g >= N_TGT) continue;
                int t = sTyp[row];
#pragma unroll
                for (int ni = 0; ni < 4; ++ni) {
                    int col = (wn << 5) + (ni << 3) + ((lid & 3) << 1);
                    float2 o;
                    o.x = acc[mi][ni][half * 2 + 0] + rootb[(t << 7) + col];
                    o.y = acc[mi][ni][half * 2 + 1] + rootb[(t << 7) + col + 1];
                    *(float2*)(out + ((size_t)g << 7) + col) = o;
                }
            }
        }
    } else {
        // ================= producer =================
        const int pw = wid - 4;
        for (int seg = 0; seg < NSEG; ++seg) {
            int buf = seg & 1;
            if (seg >= 2) BAR_SYNC(buf ? 5 : 3, 256);   // buffer freed by consumers
            uint32_t aB = sb + (buf ? OFF_A1 : OFF_A0);
            if (seg < NREL) {
                // gather-aggregate 16 rows per warp; lane covers channels lid*4..+3
#pragma unroll 2
                for (int rr = 0; rr < 16; ++rr) {
                    int row = (pw << 4) + rr;
                    int g = row0 + row;
                    float4 a = make_float4(0.f, 0.f, 0.f, 0.f);
                    if (g < N_TGT) {
                        uint32_t beg = sOfs[row * NREL + seg];
                        uint32_t end = sOfs[row * NREL + seg + 1];
                        if (useS) {
                            for (uint32_t e = beg; e < end; ++e) {
                                uint32_t s = sEl[e - e0];
                                float4 v = ((const float4*)(xs + ((size_t)s << 7)))[lid];
                                a.x += v.x; a.y += v.y; a.z += v.z; a.w += v.w;
                            }
                        } else {
                            for (uint32_t e = beg; e < end; ++e) {
                                uint32_t s = __ldg(elist + e);
                                float4 v = ((const float4*)(xs + ((size_t)s << 7)))[lid];
                                a.x += v.x; a.y += v.y; a.z += v.z; a.w += v.w;
                            }
                        }
                        float inv = 1.0f / fmaxf((float)(int)(end - beg), 1.0f);
                        a.x *= inv; a.y *= inv; a.z *= inv; a.w *= inv;
                    }
                    asm volatile("st.shared.v4.b32 [%0], {%1,%2,%3,%4};"
                        :: "r"(aB + row * (ASTR * 4) + (lid << 4)),
                           "f"(a.x), "f"(a.y), "f"(a.z), "f"(a.w) : "memory");
                }
            } else {
                // root segment: masked copy of x_target via cp.async (zfill)
                // 64 rows x 32 float4 = 2048 float4s over 128 producer threads.
                int ty = seg - NREL;
#pragma unroll
                for (int j = 0; j < 16; ++j) {
                    int i = (tid - 128) + (j << 7);   // 0..2047
                    int row = i >> 5, kv = i & 31;    // row 0..63, kv 0..31 (float4s)
                    int g = row0 + row;
                    bool ok = (g < N_TGT) && (sTyp[row] == ty);
                    cp16(aB + row * (ASTR * 4) + (kv << 4),
                         xt + ((size_t)(ok ? g : 0) << 7) + (kv << 2), ok);
                }
                CP_COMMIT(); CP_WAIT(0);
            }
            BAR_ARRIVE(buf ? 4 : 1, 256);     // A[seg] ready
        }
    }
}

extern "C" void kernel_launch(void* const* d_in, const int* in_sizes, int n_in,
                              void* d_out, int out_size)
{
    const float* x_src  = (const float*)d_in[0];
    const float* x_tgt  = (const float*)d_in[1];
    const float* rel_w  = (const float*)d_in[2];
    const float* root_w = (const float*)d_in[3];
    const float* root_b = (const float*)d_in[4];
    const int*   e_src  = (const int*)d_in[5];
    const int*   e_dst  = (const int*)d_in[6];
    const int*   e_typ  = (const int*)d_in[7];
    const int*   n_typ  = (const int*)d_in[8];
    float* out = (float*)d_out;

    void *cntp, *curp, *ofsp, *partp, *elp, *wtp;
    cudaGetSymbolAddress(&cntp,  g_bincnt);
    cudaGetSymbolAddress(&curp,  g_cursor);
    cudaGetSymbolAddress(&ofsp,  g_binofs);
    cudaGetSymbolAddress(&partp, g_part);
    cudaGetSymbolAddress(&elp,   g_elist);
    cudaGetSymbolAddress(&wtp,   g_wtf32);

    cudaMemsetAsync(cntp, 0, NBINS * sizeof(uint32_t));
    cudaMemsetAsync(curp, 0, NBINS * sizeof(uint32_t));

    hist_kernel<<<(N_EDGES + 255) / 256, 256>>>(e_dst, e_typ, (uint32_t*)cntp);
    scanA_kernel<<<NPART, 1024>>>((const uint32_t*)cntp, (uint32_t*)partp);
    scanB_kernel<<<1, 512>>>((uint32_t*)partp);
    scanC_kernel<<<NPART, 1024>>>((const uint32_t*)cntp, (const uint32_t*)partp,
                                  (uint32_t*)ofsp);
    fill_kernel<<<(N_EDGES + 255) / 256, 256>>>(e_src, e_dst, e_typ,
                                                (const uint32_t*)ofsp,
                                                (uint32_t*)curp, (uint32_t*)elp);
    prep_weights<<<(NSEG * CH * CH / 4 + 255) / 256, 256>>>(rel_w, root_w, (uint32_t*)wtp);

    cudaFuncSetAttribute(fused_kernel,
                         cudaFuncAttributeMaxDynamicSharedMemorySize, SMEM_TOTAL);
    fused_kernel<<<(N_TGT + TILE_M - 1) / TILE_M, 256, SMEM_TOTAL>>>(
        x_src, x_tgt, (const uint32_t*)wtp, root_b, n_typ,
        (const uint32_t*)ofsp, (const uint32_t*)elp, out);
}

// round 11
// speedup vs baseline: 1.0966x; 1.0067x over previous
#include <cuda_runtime.h>
#include <cstdint>

#define N_SRC   100000
#define N_TGT   50000
#define N_EDGES 600000
#define CH      128
#define NREL    7
#define NTYP    4
#define NSEG    11
#define NBINS   (N_TGT * NREL)          // 350000
#define NPART   342                     // ceil(NBINS/1024)

// Fused kernel tiling
#define TILE_M  64
#define ASTR    132                     // A row stride (words): 128 + 4 pad
#define A_BYTES (TILE_M * ASTR * 4)     // 33792 per buffer
#define BSTR    36                      // B row stride (words)
#define B_BYTES (128 * BSTR * 4)        // 18432 per stage
#define ELIST_CAP 1536

#define OFF_A0  0
#define OFF_A1  A_BYTES
#define OFF_B0  (2 * A_BYTES)
#define OFF_B1  (2 * A_BYTES + B_BYTES)
#define OFF_OFS (2 * A_BYTES + 2 * B_BYTES)
#define OFF_TYP (OFF_OFS + 452 * 4)
#define OFF_EL  (OFF_TYP + 64 * 4)
#define SMEM_TOTAL (OFF_EL + ELIST_CAP * 4)   // 112656 bytes -> 2 CTAs/SM

// Scratch (allocation-free rule: __device__ globals)
__device__ uint32_t g_bincnt[NBINS];
__device__ uint32_t g_binofs[NBINS + 1];
__device__ uint32_t g_part[NPART];
__device__ uint32_t g_elist[N_EDGES];

// ---------------- helpers ----------------
__device__ __forceinline__ uint32_t smem_u32(const void* p) {
    uint32_t a;
    asm("{ .reg .u64 t; cvta.to.shared.u64 t, %1; cvt.u32.u64 %0, t; }" : "=r"(a) : "l"(p));
    return a;
}
__device__ __forceinline__ void cp16(uint32_t dst, const void* src, bool pred) {
    asm volatile("cp.async.ca.shared.global [%0], [%1], 16, %2;"
                 :: "r"(dst), "l"(src), "r"(pred ? 16 : 0) : "memory");
}
#define CP_COMMIT() asm volatile("cp.async.commit_group;" ::: "memory")
#define CP_WAIT(n)  asm volatile("cp.async.wait_group %0;" :: "n"(n) : "memory")
#define BAR_SYNC(id, cnt)   asm volatile("bar.sync %0, %1;"   :: "r"(id), "r"(cnt) : "memory")
#define BAR_ARRIVE(id, cnt) asm volatile("bar.arrive %0, %1;" :: "r"(id), "r"(cnt) : "memory")
#define LDSM_X4(r0, r1, r2, r3, addr) \
    asm volatile("ldmatrix.sync.aligned.m8n8.x4.shared.b16 {%0,%1,%2,%3}, [%4];" \
        : "=r"(r0), "=r"(r1), "=r"(r2), "=r"(r3) : "r"(addr))

__device__ __forceinline__ void mma_tf32(float* c,
    uint32_t a0, uint32_t a1, uint32_t a2, uint32_t a3,
    uint32_t b0, uint32_t b1)
{
    asm volatile(
        "mma.sync.aligned.m16n8k8.row.col.f32.tf32.tf32.f32 "
        "{%0,%1,%2,%3}, {%4,%5,%6,%7}, {%8,%9}, {%0,%1,%2,%3};"
        : "+f"(c[0]), "+f"(c[1]), "+f"(c[2]), "+f"(c[3])
        : "r"(a0), "r"(a1), "r"(a2), "r"(a3), "r"(b0), "r"(b1));
}

// ---------------- CSR build ----------------
__global__ __launch_bounds__(256) void hist_kernel(
    const int* __restrict__ edst, const int* __restrict__ etyp,
    uint32_t* __restrict__ cnt)
{
    int e = blockIdx.x * 256 + threadIdx.x;
    if (e >= N_EDGES) return;
    atomicAdd(&cnt[__ldg(edst + e) * NREL + __ldg(etyp + e)], 1u);
}

__global__ __launch_bounds__(1024) void scanA_kernel(
    const uint32_t* __restrict__ cnt, uint32_t* __restrict__ part)
{
    __shared__ uint32_t s[1024];
    int t = threadIdx.x;
    int i = blockIdx.x * 1024 + t;
    s[t] = (i < NBINS) ? cnt[i] : 0u;
    __syncthreads();
    for (int off = 512; off; off >>= 1) {
        if (t < off) s[t] += s[t + off];
        __syncthreads();
    }
    if (t == 0) part[blockIdx.x] = s[0];
}

// scanC2: per-block exclusive prefix over part[] computed locally (reduction),
// then block-local inclusive scan of cnt -> global exclusive bin offsets.
__global__ __launch_bounds__(1024) void scanC2_kernel(
    const uint32_t* __restrict__ cnt, const uint32_t* __restrict__ part,
    uint32_t* __restrict__ ofs)
{
    __shared__ uint32_t s[1024];
    __shared__ uint32_t sp[1024];
    __shared__ uint32_t blockPrefix;
    int t = threadIdx.x;
    int b = blockIdx.x;
    // prefix = sum part[0..b-1]
    uint32_t p = 0;
    for (int i = t; i < b; i += 1024) p += part[i];
    sp[t] = p;
    __syncthreads();
    for (int off = 512; off; off >>= 1) {
        if (t < off) sp[t] += sp[t + off];
        __syncthreads();
    }
    if (t == 0) blockPrefix = sp[0];
    // inclusive scan of this block's counts
    int i = b * 1024 + t;
    uint32_t v = (i < NBINS) ? cnt[i] : 0u;
    s[t] = v;
    __syncthreads();
    for (int off = 1; off < 1024; off <<= 1) {
        uint32_t x = (t >= off) ? s[t - off] : 0u;
        __syncthreads();
        s[t] += x;
        __syncthreads();
    }
    if (i < NBINS) ofs[i] = s[t] - v + blockPrefix;
    if (b == 0 && t == 0) ofs[NBINS] = N_EDGES;
}

// fill: consumes bincnt as the cursor (atomicSub); no separate cursor array.
__global__ __launch_bounds__(256) void fill_kernel(
    const int* __restrict__ esrc, const int* __restrict__ edst,
    const int* __restrict__ etyp,
    const uint32_t* __restrict__ ofs, uint32_t* __restrict__ cnt,
    uint32_t* __restrict__ elist)
{
    int e = blockIdx.x * 256 + threadIdx.x;
    if (e >= N_EDGES) return;
    int bin = __ldg(edst + e) * NREL + __ldg(etyp + e);
    uint32_t idx = atomicSub(&cnt[bin], 1u) - 1u;
    elist[ofs[bin] + idx] = (uint32_t)__ldg(esrc + e);
}

// ---------------- fused warp-specialized aggregate+GEMM ----------------
// Warps 0-3: consumers (MMA, 64x32 warp tile each).  Warps 4-7: producers
// (gather-aggregate relation A tiles; masked-copy root A tiles).
// B is cp.async'd RAW fp32 from rel_w/root_w; HMMA truncates to tf32.
// Named barriers: 1/4 = A buf even/odd ready; 3/5 = A buf even/odd free;
// 2 = consumer-local B staging.
__global__ __launch_bounds__(256, 2) void fused_kernel(
    const float* __restrict__ xs, const float* __restrict__ xt,
    const float* __restrict__ relw, const float* __restrict__ rootw,
    const float* __restrict__ rootb, const int* __restrict__ ttype,
    const uint32_t* __restrict__ binofs, const uint32_t* __restrict__ elist,
    float* __restrict__ out)
{
    extern __shared__ char smc[];
    const uint32_t sb = smem_u32(smc);
    uint32_t* sOfs = (uint32_t*)(smc + OFF_OFS);
    int*      sTyp = (int*)(smc + OFF_TYP);
    uint32_t* sEl  = (uint32_t*)(smc + OFF_EL);

    const int tid = threadIdx.x;
    const int wid = tid >> 5;
    const int lid = tid & 31;
    const int row0 = blockIdx.x * TILE_M;

    // preload CSR offsets (449 used) + node types
    for (int i = tid; i < 449; i += 256) {
        int idx = row0 * NREL + i;
        if (idx > NBINS) idx = NBINS;
        sOfs[i] = binofs[idx];
    }
    if (tid < TILE_M) {
        int g = row0 + tid;
        sTyp[tid] = (g < N_TGT) ? ttype[g] : -1;
    }
    __syncthreads();
    const uint32_t e0 = sOfs[0];
    const int nEdge = (int)(sOfs[448] - e0);
    const bool useS = (nEdge <= ELIST_CAP);
    if (useS)
        for (int i = tid; i < nEdge; i += 256) sEl[i] = elist[e0 + i];
    __syncthreads();

    if (wid < 4) {
        // ================= consumer =================
        const int wn = wid;
        float acc[4][4][4];
#pragma unroll
        for (int mi = 0; mi < 4; ++mi)
#pragma unroll
            for (int ni = 0; ni < 4; ++ni)
#pragma unroll
                for (int q = 0; q < 4; ++q) acc[mi][ni][q] = 0.0f;

        auto issueB = [&](int ci, int stage) {
            int seg = ci >> 2, k0 = (ci & 3) << 5;
            const float* wsrc = (seg < NREL)
                ? relw  + ((size_t)seg << 14) + k0
                : rootw + ((size_t)(seg - NREL) << 14) + k0;
            uint32_t bB = sb + (stage ? OFF_B1 : OFF_B0);
#pragma unroll
            for (int j = 0; j < 8; ++j) {
                int i = tid + (j << 7);        // 0..1023
                int c = i >> 3, kv = i & 7;
                cp16(bB + c * (BSTR * 4) + (kv << 4), wsrc + (c << 7) + (kv << 2), true);
            }
        };
        issueB(0, 0); CP_COMMIT();
        issueB(1, 1); CP_COMMIT();

        // ldmatrix lane addressing (R7-proven pattern)
        const uint32_t laneA = (uint32_t)((lid & 15) * (ASTR * 4) + ((lid >> 4) << 4));
        const uint32_t laneB = (uint32_t)(((wn << 5) + ((lid >> 4) << 3) + (lid & 7)) * (BSTR * 4)
                                          + (((lid >> 3) & 1) << 4));

        for (int ci = 0; ci < 44; ++ci) {
            int seg = ci >> 2, stage = ci & 1, buf = seg & 1;
            if ((ci & 3) == 0) BAR_SYNC(buf ? 4 : 1, 256);   // A[seg] ready
            CP_WAIT(1);                                      // B chunk ci landed (this thread)
            BAR_SYNC(2, 128);                                // ...and for all consumers
            const uint32_t aA = sb + (buf ? OFF_A1 : OFF_A0) + laneA + ((uint32_t)(ci & 3) << 7);
            const uint32_t bA = sb + (stage ? OFF_B1 : OFF_B0) + laneB;
#pragma unroll
            for (int ks = 0; ks < 4; ++ks) {
                const uint32_t ko = (uint32_t)(ks << 5);
                uint32_t b01[4], b23[4];
                LDSM_X4(b01[0], b01[1], b01[2], b01[3], bA + ko);
                LDSM_X4(b23[0], b23[1], b23[2], b23[3], bA + 16u * BSTR * 4 + ko);
#pragma unroll
                for (int mi = 0; mi < 4; ++mi) {
                    uint32_t a[4];
                    LDSM_X4(a[0], a[1], a[2], a[3], aA + (uint32_t)mi * (16 * ASTR * 4) + ko);
                    mma_tf32(acc[mi][0], a[0], a[1], a[2], a[3], b01[0], b01[1]);
                    mma_tf32(acc[mi][1], a[0], a[1], a[2], a[3], b01[2], b01[3]);
                    mma_tf32(acc[mi][2], a[0], a[1], a[2], a[3], b23[0], b23[1]);
                    mma_tf32(acc[mi][3], a[0], a[1], a[2], a[3], b23[2], b23[3]);
                }
            }
            BAR_SYNC(2, 128);                 // all consumers done with B stage
            if (ci + 2 < 44) issueB(ci + 2, stage);
            CP_COMMIT();                      // uniform group accounting
            if ((ci & 3) == 3) BAR_ARRIVE(buf ? 5 : 3, 256);  // A[seg] free
        }

        // epilogue: bias + store
#pragma unroll
        for (int mi = 0; mi < 4; ++mi) {
#pragma unroll
            for (int half = 0; half < 2; ++half) {
                int row = (mi << 4) + (half << 3) + (lid >> 2);
                int g = row0 + row;
                if (g >= N_TGT) continue;
                int t = sTyp[row];
#pragma unroll
                for (int ni = 0; ni < 4; ++ni) {
                    int col = (wn << 5) + (ni << 3) + ((lid & 3) << 1);
                    float2 o;
                    o.x = acc[mi][ni][half * 2 + 0] + rootb[(t << 7) + col];
                    o.y = acc[mi][ni][half * 2 + 1] + rootb[(t << 7) + col + 1];
                    *(float2*)(out + ((size_t)g << 7) + col) = o;
                }
            }
        }
    } else {
        // ================= producer =================
        const int pw = wid - 4;
        for (int seg = 0; seg < NSEG; ++seg) {
            int buf = seg & 1;
            if (seg >= 2) BAR_SYNC(buf ? 5 : 3, 256);   // buffer freed by consumers
            uint32_t aB = sb + (buf ? OFF_A1 : OFF_A0);
            if (seg < NREL) {
                // gather-aggregate 16 rows per warp; lane covers channels lid*4..+3
#pragma unroll 2
                for (int rr = 0; rr < 16; ++rr) {
                    int row = (pw << 4) + rr;
                    int g = row0 + row;
                    float4 a = make_float4(0.f, 0.f, 0.f, 0.f);
                    if (g < N_TGT) {
                        uint32_t beg = sOfs[row * NREL + seg];
                        uint32_t end = sOfs[row * NREL + seg + 1];
                        if (useS) {
                            for (uint32_t e = beg; e < end; ++e) {
                                uint32_t s = sEl[e - e0];
                                float4 v = ((const float4*)(xs + ((size_t)s << 7)))[lid];
                                a.x += v.x; a.y += v.y; a.z += v.z; a.w += v.w;
                            }
                        } else {
                            for (uint32_t e = beg; e < end; ++e) {
                                uint32_t s = __ldg(elist + e);
                                float4 v = ((const float4*)(xs + ((size_t)s << 7)))[lid];
                                a.x += v.x; a.y += v.y; a.z += v.z; a.w += v.w;
                            }
                        }
                        float inv = 1.0f / fmaxf((float)(int)(end - beg), 1.0f);
                        a.x *= inv; a.y *= inv; a.z *= inv; a.w *= inv;
                    }
                    asm volatile("st.shared.v4.b32 [%0], {%1,%2,%3,%4};"
                        :: "r"(aB + row * (ASTR * 4) + (lid << 4)),
                           "f"(a.x), "f"(a.y), "f"(a.z), "f"(a.w) : "memory");
                }
            } else {
                // root segment: masked copy of x_target via cp.async (zfill)
                // 64 rows x 32 float4 = 2048 float4s over 128 producer threads.
                int ty = seg - NREL;
#pragma unroll
                for (int j = 0; j < 16; ++j) {
                    int i = (tid - 128) + (j << 7);   // 0..2047
                    int row = i >> 5, kv = i & 31;    // row 0..63, kv 0..31 (float4s)
                    int g = row0 + row;
                    bool ok = (g < N_TGT) && (sTyp[row] == ty);
                    cp16(aB + row * (ASTR * 4) + (kv << 4),
                         xt + ((size_t)(ok ? g : 0) << 7) + (kv << 2), ok);
                }
                CP_COMMIT(); CP_WAIT(0);
            }
            BAR_ARRIVE(buf ? 4 : 1, 256);     // A[seg] ready
        }
    }
}

extern "C" void kernel_launch(void* const* d_in, const int* in_sizes, int n_in,
                              void* d_out, int out_size)
{
    const float* x_src  = (const float*)d_in[0];
    const float* x_tgt  = (const float*)d_in[1];
    const float* rel_w  = (const float*)d_in[2];
    const float* root_w = (const float*)d_in[3];
    const float* root_b = (const float*)d_in[4];
    const int*   e_src  = (const int*)d_in[5];
    const int*   e_dst  = (const int*)d_in[6];
    const int*   e_typ  = (const int*)d_in[7];
    const int*   n_typ  = (const int*)d_in[8];
    float* out = (float*)d_out;

    void *cntp, *ofsp, *partp, *elp;
    cudaGetSymbolAddress(&cntp,  g_bincnt);
    cudaGetSymbolAddress(&ofsp,  g_binofs);
    cudaGetSymbolAddress(&partp, g_part);
    cudaGetSymbolAddress(&elp,   g_elist);

    // Launch order matters for ncu -s 5: fused_kernel is capture index 5.
    cudaMemsetAsync(cntp, 0, NBINS * sizeof(uint32_t));                    // 0
    hist_kernel<<<(N_EDGES + 255) / 256, 256>>>(e_dst, e_typ,              // 1
                                                (uint32_t*)cntp);
    scanA_kernel<<<NPART, 1024>>>((const uint32_t*)cntp, (uint32_t*)partp);// 2
    scanC2_kernel<<<NPART, 1024>>>((const uint32_t*)cntp,                  // 3
                                   (const uint32_t*)partp, (uint32_t*)ofsp);
    fill_kernel<<<(N_EDGES + 255) / 256, 256>>>(e_src, e_dst, e_typ,       // 4
                                                (const uint32_t*)ofsp,
                                                (uint32_t*)cntp, (uint32_t*)elp);

    cudaFuncSetAttribute(fused_kernel,
                         cudaFuncAttributeMaxDynamicSharedMemorySize, SMEM_TOTAL);
    fused_kernel<<<(N_TGT + TILE_M - 1) / TILE_M, 256, SMEM_TOTAL>>>(      // 5
        x_src, x_tgt, rel_w, root_w, root_b, n_typ,
        (const uint32_t*)ofsp, (const uint32_t*)elp, out);
}